// round 3
// baseline (speedup 1.0000x reference)
#include <cuda_runtime.h>
#include <cuda_bf16.h>
#include <math.h>

// ---------------- problem constants ----------------
#define DIMN   1024
#define SEQ    2048
#define BATCH  2
#define TOK    (BATCH*SEQ)    // 4096 tokens
#define HEADS  16
#define HD     64
#define MLPD   4096
#define DEPTH  6
#define ASCALE 0.03125f       // DIM^-0.5 (reference uses full dim)

// ---------------- scratch (device globals; no cudaMalloc allowed) ----------------
__device__ float g_y   [(size_t)TOK * DIMN];        // 16 MB  (LN output)
__device__ float g_qkv [(size_t)TOK * 3 * DIMN];    // 48 MB
__device__ float g_attn[(size_t)TOK * DIMN];        // 16 MB
__device__ float g_u   [(size_t)TOK * MLPD];        // 64 MB  (MLP hidden)

// ---------------- layernorm: one block per row of 1024 ----------------
__global__ __launch_bounds__(256) void ln_kernel(
    const float* __restrict__ x, const float* __restrict__ g,
    const float* __restrict__ b, float* __restrict__ y)
{
    __shared__ float redS[8], redQ[8];
    const int row = blockIdx.x;
    const int tid = threadIdx.x;
    const float4 v = reinterpret_cast<const float4*>(x)[(size_t)row * 256 + tid];
    float s = v.x + v.y + v.z + v.w;
    float q = v.x*v.x + v.y*v.y + v.z*v.z + v.w*v.w;
    #pragma unroll
    for (int off = 16; off; off >>= 1) {
        s += __shfl_xor_sync(0xffffffffu, s, off);
        q += __shfl_xor_sync(0xffffffffu, q, off);
    }
    if ((tid & 31) == 0) { redS[tid >> 5] = s; redQ[tid >> 5] = q; }
    __syncthreads();
    s = 0.f; q = 0.f;
    #pragma unroll
    for (int w = 0; w < 8; w++) { s += redS[w]; q += redQ[w]; }
    const float mean = s * (1.0f / DIMN);
    const float var  = q * (1.0f / DIMN) - mean * mean;
    const float rstd = rsqrtf(var + 1e-5f);
    const float4 gg = reinterpret_cast<const float4*>(g)[tid];
    const float4 bb = reinterpret_cast<const float4*>(b)[tid];
    float4 o;
    o.x = (v.x - mean) * rstd * gg.x + bb.x;
    o.y = (v.y - mean) * rstd * gg.y + bb.y;
    o.z = (v.z - mean) * rstd * gg.z + bb.z;
    o.w = (v.w - mean) * rstd * gg.w + bb.w;
    reinterpret_cast<float4*>(y)[(size_t)row * 256 + tid] = o;
}

// ---------------- SGEMM 128x128x8, 256 threads, 8x8/thread ----------------
// C[M,N] = op(A[M,K] @ B[K,N] + bias)  (+ C if residual). All dims multiples of tile.
#define BM 128
#define BN 128
#define BK 8
#define FLAG_RESID 1
#define FLAG_GELU  2

__device__ __forceinline__ float gelu_exact(float x) {
    return 0.5f * x * (1.0f + erff(x * 0.70710678118654752f));
}

__global__ __launch_bounds__(256, 2) void sgemm_kernel(
    int M, int N, int K,
    const float* __restrict__ A, const float* __restrict__ B,
    float* __restrict__ C, const float* __restrict__ bias, int flags)
{
    __shared__ float As[2][BK][BM];
    __shared__ float Bs[2][BK][BN];
    const int tid = threadIdx.x;
    const int bm = blockIdx.y * BM;
    const int bn = blockIdx.x * BN;

    // global->smem load mapping (float4)
    const int aRow = tid >> 1;            // 0..127
    const int aCol = (tid & 1) << 2;      // 0 or 4
    const int bRow = tid >> 5;            // 0..7
    const int bCol = (tid & 31) << 2;     // 0..124
    const float* Ap = A + (size_t)(bm + aRow) * K + aCol;
    const float* Bp = B + (size_t)bRow * N + bn + bCol;

    // compute mapping
    const int tx = tid & 15, ty = tid >> 4;
    const int cr = ty << 3, cc = tx << 3;

    float acc[8][8];
    #pragma unroll
    for (int i = 0; i < 8; i++)
        #pragma unroll
        for (int j = 0; j < 8; j++) acc[i][j] = 0.f;

    float4 a0 = *reinterpret_cast<const float4*>(Ap);
    float4 b0 = *reinterpret_cast<const float4*>(Bp);
    As[0][aCol + 0][aRow] = a0.x; As[0][aCol + 1][aRow] = a0.y;
    As[0][aCol + 2][aRow] = a0.z; As[0][aCol + 3][aRow] = a0.w;
    *reinterpret_cast<float4*>(&Bs[0][bRow][bCol]) = b0;
    __syncthreads();

    int stage = 0;
    for (int k0 = BK; k0 <= K; k0 += BK) {
        float4 an = make_float4(0.f, 0.f, 0.f, 0.f);
        float4 bn4 = make_float4(0.f, 0.f, 0.f, 0.f);
        const bool more = (k0 < K);
        if (more) {
            an  = *reinterpret_cast<const float4*>(Ap + k0);
            bn4 = *reinterpret_cast<const float4*>(Bp + (size_t)k0 * N);
        }
        #pragma unroll
        for (int kk = 0; kk < BK; kk++) {
            float ra[8], rb[8];
            *reinterpret_cast<float4*>(&ra[0]) = *reinterpret_cast<const float4*>(&As[stage][kk][cr]);
            *reinterpret_cast<float4*>(&ra[4]) = *reinterpret_cast<const float4*>(&As[stage][kk][cr + 4]);
            *reinterpret_cast<float4*>(&rb[0]) = *reinterpret_cast<const float4*>(&Bs[stage][kk][cc]);
            *reinterpret_cast<float4*>(&rb[4]) = *reinterpret_cast<const float4*>(&Bs[stage][kk][cc + 4]);
            #pragma unroll
            for (int i = 0; i < 8; i++)
                #pragma unroll
                for (int j = 0; j < 8; j++)
                    acc[i][j] = fmaf(ra[i], rb[j], acc[i][j]);
        }
        if (more) {
            stage ^= 1;
            As[stage][aCol + 0][aRow] = an.x; As[stage][aCol + 1][aRow] = an.y;
            As[stage][aCol + 2][aRow] = an.z; As[stage][aCol + 3][aRow] = an.w;
            *reinterpret_cast<float4*>(&Bs[stage][bRow][bCol]) = bn4;
            __syncthreads();
        }
    }

    // epilogue
    float bv[8];
    if (bias) {
        *reinterpret_cast<float4*>(&bv[0]) = *reinterpret_cast<const float4*>(bias + bn + cc);
        *reinterpret_cast<float4*>(&bv[4]) = *reinterpret_cast<const float4*>(bias + bn + cc + 4);
    } else {
        #pragma unroll
        for (int j = 0; j < 8; j++) bv[j] = 0.f;
    }
    #pragma unroll
    for (int i = 0; i < 8; i++) {
        float* Cp = C + (size_t)(bm + cr + i) * N + bn + cc;
        #pragma unroll
        for (int jj = 0; jj < 8; jj += 4) {
            float v[4];
            #pragma unroll
            for (int u = 0; u < 4; u++) {
                float t = acc[i][jj + u] + bv[jj + u];
                if (flags & FLAG_GELU) t = gelu_exact(t);
                v[u] = t;
            }
            float4 out4;
            if (flags & FLAG_RESID) {
                const float4 c0 = *reinterpret_cast<const float4*>(Cp + jj);
                out4 = make_float4(c0.x + v[0], c0.y + v[1], c0.z + v[2], c0.w + v[3]);
            } else {
                out4 = make_float4(v[0], v[1], v[2], v[3]);
            }
            *reinterpret_cast<float4*>(Cp + jj) = out4;
        }
    }
}

// ---------------- fused flash attention (per batch*head), hd=64 ----------------
// BR=32 query rows per CTA, BC=64 kv cols per tile, 256 threads (16x16 grid,
// each thread owns a 2x4 tile of S and a 2x4 tile of O). 48 KB static smem.
#define AR 32
#define AC 64

__global__ __launch_bounds__(256) void attn_kernel(
    const float* __restrict__ qkv, float* __restrict__ out)
{
    __shared__ float Qs [AR][HD];   //  8 KB, pre-scaled by ASCALE
    __shared__ float Kts[HD][AC];   // 16 KB, K transposed: [d][c]
    __shared__ float Vs [AC][HD];   // 16 KB
    __shared__ float Ps [AR][AC];   //  8 KB

    const int tid = threadIdx.x;
    const int bh  = blockIdx.y;
    const int bb  = bh >> 4, h = bh & 15;
    const int q0  = blockIdx.x * AR;
    const size_t base = (size_t)bb * SEQ * 3 * DIMN;
    const int hoff = h * HD;

    // load Q tile (scaled)
    for (int i = tid; i < AR * (HD / 4); i += 256) {
        const int r = i >> 4, c4 = (i & 15) << 2;
        const float4 v = *reinterpret_cast<const float4*>(
            qkv + base + (size_t)(q0 + r) * (3 * DIMN) + hoff + c4);
        Qs[r][c4 + 0] = v.x * ASCALE; Qs[r][c4 + 1] = v.y * ASCALE;
        Qs[r][c4 + 2] = v.z * ASCALE; Qs[r][c4 + 3] = v.w * ASCALE;
    }

    const int tx = tid & 15, ty = tid >> 4;
    const int r0 = ty << 1;     // 2 query rows
    const int c0 = tx << 2;     // 4 score cols; also 4 O dims

    float m0 = -1e30f, m1 = -1e30f, l0 = 0.f, l1 = 0.f;
    float o0[4] = {0.f, 0.f, 0.f, 0.f}, o1[4] = {0.f, 0.f, 0.f, 0.f};

    for (int kb = 0; kb < SEQ; kb += AC) {
        __syncthreads();  // previous tile fully consumed (also orders Q stores on iter 0)
        for (int i = tid; i < AC * (HD / 4); i += 256) {
            const int c = i >> 4, d4 = (i & 15) << 2;
            const float* rowp = qkv + base + (size_t)(kb + c) * (3 * DIMN) + hoff;
            const float4 kv = *reinterpret_cast<const float4*>(rowp + DIMN + d4);
            Kts[d4 + 0][c] = kv.x; Kts[d4 + 1][c] = kv.y;
            Kts[d4 + 2][c] = kv.z; Kts[d4 + 3][c] = kv.w;
            *reinterpret_cast<float4*>(&Vs[c][d4]) =
                *reinterpret_cast<const float4*>(rowp + 2 * DIMN + d4);
        }
        __syncthreads();

        // S = (Q*scale) K^T   -> s0/s1 [4]
        float s0[4] = {0.f, 0.f, 0.f, 0.f}, s1[4] = {0.f, 0.f, 0.f, 0.f};
        #pragma unroll
        for (int kd = 0; kd < HD; kd += 4) {
            float qa[4], qb[4];
            *reinterpret_cast<float4*>(qa) = *reinterpret_cast<const float4*>(&Qs[r0][kd]);
            *reinterpret_cast<float4*>(qb) = *reinterpret_cast<const float4*>(&Qs[r0 + 1][kd]);
            #pragma unroll
            for (int u = 0; u < 4; u++) {
                float kf[4];
                *reinterpret_cast<float4*>(kf) = *reinterpret_cast<const float4*>(&Kts[kd + u][c0]);
                #pragma unroll
                for (int j = 0; j < 4; j++) {
                    s0[j] = fmaf(qa[u], kf[j], s0[j]);
                    s1[j] = fmaf(qb[u], kf[j], s1[j]);
                }
            }
        }
        // online softmax (row reduction over the 16 lanes sharing a row group)
        float rm0 = fmaxf(fmaxf(s0[0], s0[1]), fmaxf(s0[2], s0[3]));
        float rm1 = fmaxf(fmaxf(s1[0], s1[1]), fmaxf(s1[2], s1[3]));
        #pragma unroll
        for (int off = 8; off; off >>= 1) {
            rm0 = fmaxf(rm0, __shfl_xor_sync(0xffffffffu, rm0, off));
            rm1 = fmaxf(rm1, __shfl_xor_sync(0xffffffffu, rm1, off));
        }
        const float mn0 = fmaxf(m0, rm0), mn1 = fmaxf(m1, rm1);
        const float al0 = __expf(m0 - mn0), al1 = __expf(m1 - mn1);
        m0 = mn0; m1 = mn1;
        float rs0 = 0.f, rs1 = 0.f;
        #pragma unroll
        for (int j = 0; j < 4; j++) {
            s0[j] = __expf(s0[j] - mn0); rs0 += s0[j];
            s1[j] = __expf(s1[j] - mn1); rs1 += s1[j];
        }
        #pragma unroll
        for (int off = 8; off; off >>= 1) {
            rs0 += __shfl_xor_sync(0xffffffffu, rs0, off);
            rs1 += __shfl_xor_sync(0xffffffffu, rs1, off);
        }
        l0 = l0 * al0 + rs0; l1 = l1 * al1 + rs1;
        #pragma unroll
        for (int j = 0; j < 4; j++) { o0[j] *= al0; o1[j] *= al1; }
        *reinterpret_cast<float4*>(&Ps[r0][c0])     = make_float4(s0[0], s0[1], s0[2], s0[3]);
        *reinterpret_cast<float4*>(&Ps[r0 + 1][c0]) = make_float4(s1[0], s1[1], s1[2], s1[3]);
        __syncthreads();

        // O += P V
        #pragma unroll
        for (int c = 0; c < AC; c += 4) {
            float pa[4], pb[4];
            *reinterpret_cast<float4*>(pa) = *reinterpret_cast<const float4*>(&Ps[r0][c]);
            *reinterpret_cast<float4*>(pb) = *reinterpret_cast<const float4*>(&Ps[r0 + 1][c]);
            #pragma unroll
            for (int u = 0; u < 4; u++) {
                float vf[4];
                *reinterpret_cast<float4*>(vf) = *reinterpret_cast<const float4*>(&Vs[c + u][c0]);
                #pragma unroll
                for (int j = 0; j < 4; j++) {
                    o0[j] = fmaf(pa[u], vf[j], o0[j]);
                    o1[j] = fmaf(pb[u], vf[j], o1[j]);
                }
            }
        }
    }

    const float il0 = 1.0f / l0, il1 = 1.0f / l1;
    const size_t obase = ((size_t)bb * SEQ + q0) * DIMN + hoff + c0;
    *reinterpret_cast<float4*>(out + obase + (size_t)r0 * DIMN) =
        make_float4(o0[0] * il0, o0[1] * il0, o0[2] * il0, o0[3] * il0);
    *reinterpret_cast<float4*>(out + obase + (size_t)(r0 + 1) * DIMN) =
        make_float4(o1[0] * il1, o1[1] * il1, o1[2] * il1, o1[3] * il1);
}

// ---------------- launch ----------------
extern "C" void kernel_launch(void* const* d_in, const int* in_sizes, int n_in,
                              void* d_out, int out_size)
{
    const float* x    = (const float*)d_in[0];
    const float* Wqkv = (const float*)d_in[1];
    const float* Wout = (const float*)d_in[2];
    const float* bout = (const float*)d_in[3];
    const float* ln1g = (const float*)d_in[4];
    const float* ln1b = (const float*)d_in[5];
    const float* ln2g = (const float*)d_in[6];
    const float* ln2b = (const float*)d_in[7];
    const float* W1   = (const float*)d_in[8];
    const float* b1   = (const float*)d_in[9];
    const float* W2   = (const float*)d_in[10];
    const float* b2   = (const float*)d_in[11];
    float* h = (float*)d_out;   // residual stream lives in d_out

    float *y, *qkv, *attn, *u;
    cudaGetSymbolAddress((void**)&y,    g_y);
    cudaGetSymbolAddress((void**)&qkv,  g_qkv);
    cudaGetSymbolAddress((void**)&attn, g_attn);
    cudaGetSymbolAddress((void**)&u,    g_u);

    cudaMemcpyAsync(h, x, (size_t)TOK * DIMN * sizeof(float), cudaMemcpyDeviceToDevice);

    for (int l = 0; l < DEPTH; l++) {
        const float* wqkv = Wqkv + (size_t)l * DIMN * 3 * DIMN;
        const float* wout = Wout + (size_t)l * DIMN * DIMN;
        const float* bo   = bout + (size_t)l * DIMN;
        const float* g1   = ln1g + (size_t)l * DIMN;
        const float* bb1  = ln1b + (size_t)l * DIMN;
        const float* g2   = ln2g + (size_t)l * DIMN;
        const float* bb2  = ln2b + (size_t)l * DIMN;
        const float* w1   = W1   + (size_t)l * DIMN * MLPD;
        const float* bf1  = b1   + (size_t)l * MLPD;
        const float* w2   = W2   + (size_t)l * MLPD * DIMN;
        const float* bf2  = b2   + (size_t)l * DIMN;

        ln_kernel<<<TOK, 256>>>(h, g1, bb1, y);
        sgemm_kernel<<<dim3(3 * DIMN / BN, TOK / BM), 256>>>(
            TOK, 3 * DIMN, DIMN, y, wqkv, qkv, nullptr, 0);
        attn_kernel<<<dim3(SEQ / AR, BATCH * HEADS), 256>>>(qkv, attn);
        sgemm_kernel<<<dim3(DIMN / BN, TOK / BM), 256>>>(
            TOK, DIMN, DIMN, attn, wout, h, bo, FLAG_RESID);
        ln_kernel<<<TOK, 256>>>(h, g2, bb2, y);
        sgemm_kernel<<<dim3(MLPD / BN, TOK / BM), 256>>>(
            TOK, MLPD, DIMN, y, w1, u, bf1, FLAG_GELU);
        sgemm_kernel<<<dim3(DIMN / BN, TOK / BM), 256>>>(
            TOK, DIMN, MLPD, u, w2, h, bf2, FLAG_RESID);
    }
}

// round 9
// speedup vs baseline: 1.5967x; 1.5967x over previous
#include <cuda_runtime.h>
#include <cuda_bf16.h>
#include <math.h>
#include <stdint.h>

// ---------------- problem constants ----------------
#define DIMN   1024
#define SEQ    2048
#define BATCH  2
#define TOK    (BATCH*SEQ)    // 4096 tokens
#define HEADS  16
#define HD     64
#define MLPD   4096
#define DEPTH  6
#define ASCALE 0.03125f       // DIM^-0.5 (reference uses full dim)

#define FLAG_RESID 1
#define FLAG_GELU  2
#define FLAG_PACK  4

// SW128 swizzle (Swizzle<3,4,3>) on byte offsets within a 128B-row tile
#define SWZ(o) ((o) ^ (((o) >> 3) & 0x70))

// ---------------- scratch (device globals; no cudaMalloc allowed) ----------------
__device__ float g_qkv [(size_t)TOK * 3 * DIMN];            // fp32 QKV (attn input)
// packed hi/lo bf16 activations (tile = 128 rows x 64 k, SW128, 8192 elems)
__device__ __nv_bfloat16 g_y_hi [(size_t)TOK * DIMN];
__device__ __nv_bfloat16 g_y_lo [(size_t)TOK * DIMN];
__device__ __nv_bfloat16 g_at_hi[(size_t)TOK * DIMN];
__device__ __nv_bfloat16 g_at_lo[(size_t)TOK * DIMN];
__device__ __nv_bfloat16 g_u_hi [(size_t)TOK * MLPD];
__device__ __nv_bfloat16 g_u_lo [(size_t)TOK * MLPD];
// packed (pre-transposed [N,K], pre-swizzled, bf16 hi/lo) weights
__device__ __nv_bfloat16 g_qkv_hi[(size_t)DEPTH * DIMN * 3 * DIMN];
__device__ __nv_bfloat16 g_qkv_lo[(size_t)DEPTH * DIMN * 3 * DIMN];
__device__ __nv_bfloat16 g_wo_hi [(size_t)DEPTH * DIMN * DIMN];
__device__ __nv_bfloat16 g_wo_lo [(size_t)DEPTH * DIMN * DIMN];
__device__ __nv_bfloat16 g_w1_hi [(size_t)DEPTH * DIMN * MLPD];
__device__ __nv_bfloat16 g_w1_lo [(size_t)DEPTH * DIMN * MLPD];
__device__ __nv_bfloat16 g_w2_hi [(size_t)DEPTH * MLPD * DIMN];
__device__ __nv_bfloat16 g_w2_lo [(size_t)DEPTH * MLPD * DIMN];

// ---------------- helpers ----------------
__device__ __forceinline__ uint32_t smem_u32(const void* p) {
    uint32_t a;
    asm("{ .reg .u64 t; cvta.to.shared.u64 t, %1; cvt.u32.u64 %0, t; }"
        : "=r"(a) : "l"(p));
    return a;
}
__device__ __forceinline__ void cpasync16(uint32_t s, const void* g) {
    asm volatile("cp.async.cg.shared.global [%0], [%1], 16;" :: "r"(s), "l"(g));
}
#define CP_COMMIT() asm volatile("cp.async.commit_group;" ::: "memory")
#define CP_WAIT(n)  asm volatile("cp.async.wait_group %0;" :: "n"(n) : "memory")

#define LDM_X4(r, a)                                                          \
    asm volatile("ldmatrix.sync.aligned.m8n8.x4.shared.b16 {%0,%1,%2,%3}, [%4];" \
                 : "=r"((r)[0]), "=r"((r)[1]), "=r"((r)[2]), "=r"((r)[3])     \
                 : "r"(a))

__device__ __forceinline__ void mma_bf(float* c, const uint32_t* a,
                                       uint32_t b0, uint32_t b1) {
    asm volatile(
        "mma.sync.aligned.m16n8k16.row.col.f32.bf16.bf16.f32 "
        "{%0,%1,%2,%3}, {%4,%5,%6,%7}, {%8,%9}, {%0,%1,%2,%3};"
        : "+f"(c[0]), "+f"(c[1]), "+f"(c[2]), "+f"(c[3])
        : "r"(a[0]), "r"(a[1]), "r"(a[2]), "r"(a[3]), "r"(b0), "r"(b1));
}

__device__ __forceinline__ float gelu_exact(float x) {
    return 0.5f * x * (1.0f + erff(x * 0.70710678118654752f));
}
// pack two floats -> hi bf16 pair / lo bf16 pair
__device__ __forceinline__ void pack2(float a, float b, uint32_t& h, uint32_t& l) {
    const __nv_bfloat16 ha = __float2bfloat16(a);
    const __nv_bfloat16 hb = __float2bfloat16(b);
    const __nv_bfloat16 la = __float2bfloat16(a - __bfloat162float(ha));
    const __nv_bfloat16 lb = __float2bfloat16(b - __bfloat162float(hb));
    h = (uint32_t)__bfloat16_as_ushort(ha) | ((uint32_t)__bfloat16_as_ushort(hb) << 16);
    l = (uint32_t)__bfloat16_as_ushort(la) | ((uint32_t)__bfloat16_as_ushort(lb) << 16);
}

// ---------------- layernorm -> packed hi/lo tiles ----------------
// tile = ((row>>7)*(K/64) + (k>>6)) * 8192 elems; off = SWZ((row&127)*128 + (k&63)*2)
__global__ __launch_bounds__(256) void ln_pack(
    const float* __restrict__ x, const float* __restrict__ g,
    const float* __restrict__ b, __nv_bfloat16* __restrict__ hi,
    __nv_bfloat16* __restrict__ lo)
{
    __shared__ float redS[8], redQ[8];
    const int row = blockIdx.x;
    const int tid = threadIdx.x;
    const float4 v = reinterpret_cast<const float4*>(x)[(size_t)row * 256 + tid];
    float s = v.x + v.y + v.z + v.w;
    float q = v.x*v.x + v.y*v.y + v.z*v.z + v.w*v.w;
    #pragma unroll
    for (int off = 16; off; off >>= 1) {
        s += __shfl_xor_sync(0xffffffffu, s, off);
        q += __shfl_xor_sync(0xffffffffu, q, off);
    }
    if ((tid & 31) == 0) { redS[tid >> 5] = s; redQ[tid >> 5] = q; }
    __syncthreads();
    s = 0.f; q = 0.f;
    #pragma unroll
    for (int w = 0; w < 8; w++) { s += redS[w]; q += redQ[w]; }
    const float mean = s * (1.0f / DIMN);
    const float var  = q * (1.0f / DIMN) - mean * mean;
    const float rstd = rsqrtf(var + 1e-5f);
    const float4 gg = reinterpret_cast<const float4*>(g)[tid];
    const float4 bb = reinterpret_cast<const float4*>(b)[tid];
    float o0 = (v.x - mean) * rstd * gg.x + bb.x;
    float o1 = (v.y - mean) * rstd * gg.y + bb.y;
    float o2 = (v.z - mean) * rstd * gg.z + bb.z;
    float o3 = (v.w - mean) * rstd * gg.w + bb.w;
    uint32_t h0, l0, h1, l1;
    pack2(o0, o1, h0, l0);
    pack2(o2, o3, h1, l1);
    const int k = tid << 2;
    const size_t tile = (size_t)(row >> 7) * (DIMN / 64) + (k >> 6);
    const uint32_t off = SWZ((uint32_t)((row & 127) * 128 + ((k & 63) << 1)));
    *reinterpret_cast<uint2*>((char*)hi + tile * 16384 + off) = make_uint2(h0, h1);
    *reinterpret_cast<uint2*>((char*)lo + tile * 16384 + off) = make_uint2(l0, l1);
}

// ---------------- weight prep: fp32 W[K,N] -> packed hi/lo bf16 tiles ----------
__global__ __launch_bounds__(256) void prep_kernel(
    const float* __restrict__ W, __nv_bfloat16* __restrict__ hi,
    __nv_bfloat16* __restrict__ lo, int K, int N)
{
    __shared__ __nv_bfloat16 shH[8192], shL[8192];
    const int nt = blockIdx.x, kc = blockIdx.y, layer = blockIdx.z;
    const float* Wp = W + (size_t)layer * K * N;
    const int tid = threadIdx.x;
    #pragma unroll
    for (int i = 0; i < 8; i++) {
        const int idx = tid + (i << 8);
        const int r  = idx >> 5;               // k_local 0..63
        const int c4 = (idx & 31) << 2;        // n_local 0..124
        const float4 v = *reinterpret_cast<const float4*>(
            Wp + (size_t)(kc * 64 + r) * N + nt * 128 + c4);
        const float f[4] = {v.x, v.y, v.z, v.w};
        #pragma unroll
        for (int j = 0; j < 4; j++) {
            const __nv_bfloat16 h = __float2bfloat16(f[j]);
            const __nv_bfloat16 l = __float2bfloat16(f[j] - __bfloat162float(h));
            const uint32_t sw = SWZ((uint32_t)((c4 + j) * 128 + r * 2));
            shH[sw >> 1] = h;
            shL[sw >> 1] = l;
        }
    }
    __syncthreads();
    const size_t tb = ((size_t)layer * gridDim.x * gridDim.y +
                       (size_t)nt * gridDim.y + kc) * 8192;
    uint4* dH = reinterpret_cast<uint4*>(hi + tb);
    uint4* dL = reinterpret_cast<uint4*>(lo + tb);
    const uint4* sH = reinterpret_cast<const uint4*>(shH);
    const uint4* sL = reinterpret_cast<const uint4*>(shL);
    #pragma unroll
    for (int i = 0; i < 4; i++) {
        const int idx = tid + (i << 8);
        dH[idx] = sH[idx];
        dL[idx] = sL[idx];
    }
}

// ---------------- mma.sync split-bf16 GEMM ----------------
// C[M,N] = A@W (+bias)(+gelu)(+resid | ->pack). 128x128 CTA tile, K-chunk 64,
// 3-stage cp.async pipeline, 8 warps each 32(m)x64(n).
#define STAGES 3
#define STG_BYTES 65536          // Ahi 16K | Alo 16K | Bhi 16K | Blo 16K
#define GEMM_SMEM (STAGES * STG_BYTES)

__global__ __launch_bounds__(256, 1) void gemm_mma(
    int M, int N, int K,
    const __nv_bfloat16* __restrict__ Ahi, const __nv_bfloat16* __restrict__ Alo,
    const __nv_bfloat16* __restrict__ Bhi, const __nv_bfloat16* __restrict__ Blo,
    float* __restrict__ C, const float* __restrict__ bias,
    __nv_bfloat16* __restrict__ Phi, __nv_bfloat16* __restrict__ Plo,
    int packNC, int flags)
{
    extern __shared__ __align__(1024) char smem[];
    const uint32_t sb = smem_u32(smem);
    const int tid = threadIdx.x;
    const int wid = tid >> 5, lane = tid & 31;
    const int NC = K >> 6;
    const int bm = blockIdx.y << 7, bn = blockIdx.x << 7;
    const size_t at0 = (size_t)blockIdx.y * NC;
    const size_t bt0 = (size_t)blockIdx.x * NC;

    // ---- prologue: fill pipeline ----
    #pragma unroll
    for (int s = 0; s < STAGES; s++) {
        const char* ga_h = (const char*)Ahi + (at0 + s) * 16384;
        const char* ga_l = (const char*)Alo + (at0 + s) * 16384;
        const char* gb_h = (const char*)Bhi + (bt0 + s) * 16384;
        const char* gb_l = (const char*)Blo + (bt0 + s) * 16384;
        const uint32_t ds = sb + s * STG_BYTES;
        #pragma unroll
        for (int i = 0; i < 4; i++) {
            const int idx = (tid + (i << 8)) << 4;   // byte offset 0..16368
            cpasync16(ds +     0 + idx, ga_h + idx);
            cpasync16(ds + 16384 + idx, ga_l + idx);
            cpasync16(ds + 32768 + idx, gb_h + idx);
            cpasync16(ds + 49152 + idx, gb_l + idx);
        }
        CP_COMMIT();
    }

    float acc[2][8][4];
    #pragma unroll
    for (int i = 0; i < 2; i++)
        #pragma unroll
        for (int j = 0; j < 8; j++)
            #pragma unroll
            for (int u = 0; u < 4; u++) acc[i][j][u] = 0.f;

    const int wm0 = (wid & 3) << 5;     // warp m offset (0..96)
    const int wn0 = (wid >> 2) << 6;    // warp n offset (0 or 64)
    uint32_t aoff[2], boff[4];
    #pragma unroll
    for (int mt = 0; mt < 2; mt++)
        aoff[mt] = (uint32_t)((wm0 + (mt << 4) + (lane & 15)) * 128 + ((lane >> 4) << 4));
    #pragma unroll
    for (int g = 0; g < 4; g++)
        boff[g] = (uint32_t)((wn0 + (g << 4) + (lane & 7) + ((lane >> 1) & 8)) * 128 +
                             ((lane & 8) << 1));

    for (int c = 0; c < NC; c++) {
        // wait for group c: pending-after = min(c+STAGES,NC) - c - 1
        const int n_after = (c + STAGES <= NC ? STAGES : NC - c) - 1;
        if (n_after >= 2) CP_WAIT(2);
        else if (n_after == 1) CP_WAIT(1);
        else CP_WAIT(0);
        __syncthreads();

        const uint32_t stb = sb + (uint32_t)(c % STAGES) * STG_BYTES;
        #pragma unroll
        for (int ks = 0; ks < 4; ks++) {
            const uint32_t kb = (uint32_t)(ks << 5);
            uint32_t ah[2][4], al[2][4], bf[4][4];
            #pragma unroll
            for (int mt = 0; mt < 2; mt++) {
                const uint32_t o = aoff[mt] + kb;
                LDM_X4(ah[mt], stb + SWZ(o));
            }
            #pragma unroll
            for (int g = 0; g < 4; g++) {
                const uint32_t o = boff[g] + kb;
                LDM_X4(bf[g], stb + 32768 + SWZ(o));
            }
            #pragma unroll
            for (int mt = 0; mt < 2; mt++)
                #pragma unroll
                for (int g = 0; g < 4; g++) {
                    mma_bf(acc[mt][2*g],   ah[mt], bf[g][0], bf[g][1]);
                    mma_bf(acc[mt][2*g+1], ah[mt], bf[g][2], bf[g][3]);
                }
            #pragma unroll
            for (int mt = 0; mt < 2; mt++) {
                const uint32_t o = aoff[mt] + kb;
                LDM_X4(al[mt], stb + 16384 + SWZ(o));
            }
            #pragma unroll
            for (int mt = 0; mt < 2; mt++)
                #pragma unroll
                for (int g = 0; g < 4; g++) {
                    mma_bf(acc[mt][2*g],   al[mt], bf[g][0], bf[g][1]);
                    mma_bf(acc[mt][2*g+1], al[mt], bf[g][2], bf[g][3]);
                }
            #pragma unroll
            for (int g = 0; g < 4; g++) {
                const uint32_t o = boff[g] + kb;
                LDM_X4(bf[g], stb + 49152 + SWZ(o));
            }
            #pragma unroll
            for (int mt = 0; mt < 2; mt++)
                #pragma unroll
                for (int g = 0; g < 4; g++) {
                    mma_bf(acc[mt][2*g],   ah[mt], bf[g][0], bf[g][1]);
                    mma_bf(acc[mt][2*g+1], ah[mt], bf[g][2], bf[g][3]);
                }
        }
        __syncthreads();

        const int cn = c + STAGES;
        if (cn < NC) {
            const char* ga_h = (const char*)Ahi + (at0 + cn) * 16384;
            const char* ga_l = (const char*)Alo + (at0 + cn) * 16384;
            const char* gb_h = (const char*)Bhi + (bt0 + cn) * 16384;
            const char* gb_l = (const char*)Blo + (bt0 + cn) * 16384;
            const uint32_t ds = sb + (uint32_t)(c % STAGES) * STG_BYTES;
            #pragma unroll
            for (int i = 0; i < 4; i++) {
                const int idx = (tid + (i << 8)) << 4;
                cpasync16(ds +     0 + idx, ga_h + idx);
                cpasync16(ds + 16384 + idx, ga_l + idx);
                cpasync16(ds + 32768 + idx, gb_h + idx);
                cpasync16(ds + 49152 + idx, gb_l + idx);
            }
        }
        CP_COMMIT();   // commit even if empty to keep group accounting aligned
    }

    // ---- epilogue ----
    #pragma unroll
    for (int mt = 0; mt < 2; mt++) {
        const int r0 = bm + wm0 + (mt << 4) + (lane >> 2);
        #pragma unroll
        for (int nt = 0; nt < 8; nt++) {
            const int col = bn + wn0 + (nt << 3) + ((lane & 3) << 1);
            float va0 = acc[mt][nt][0], va1 = acc[mt][nt][1];
            float vb0 = acc[mt][nt][2], vb1 = acc[mt][nt][3];
            if (bias) {
                const float2 bv = *reinterpret_cast<const float2*>(bias + col);
                va0 += bv.x; va1 += bv.y; vb0 += bv.x; vb1 += bv.y;
            }
            if (flags & FLAG_GELU) {
                va0 = gelu_exact(va0); va1 = gelu_exact(va1);
                vb0 = gelu_exact(vb0); vb1 = gelu_exact(vb1);
            }
            if (flags & FLAG_PACK) {
                #pragma unroll
                for (int rr = 0; rr < 2; rr++) {
                    const int r = r0 + (rr << 3);
                    const float pa = rr ? vb0 : va0;
                    const float pb = rr ? vb1 : va1;
                    uint32_t hv, lv;
                    pack2(pa, pb, hv, lv);
                    const size_t tile = (size_t)(r >> 7) * packNC + (col >> 6);
                    const uint32_t off = SWZ((uint32_t)((r & 127) * 128 + ((col & 63) << 1)));
                    *reinterpret_cast<uint32_t*>((char*)Phi + tile * 16384 + off) = hv;
                    *reinterpret_cast<uint32_t*>((char*)Plo + tile * 16384 + off) = lv;
                }
            } else {
                float* p0 = C + (size_t)r0 * N + col;
                float* p1 = C + (size_t)(r0 + 8) * N + col;
                if (flags & FLAG_RESID) {
                    const float2 c0 = *reinterpret_cast<const float2*>(p0);
                    const float2 c1 = *reinterpret_cast<const float2*>(p1);
                    va0 += c0.x; va1 += c0.y; vb0 += c1.x; vb1 += c1.y;
                }
                *reinterpret_cast<float2*>(p0) = make_float2(va0, va1);
                *reinterpret_cast<float2*>(p1) = make_float2(vb0, vb1);
            }
        }
    }
}

// ---------------- fused flash attention (per batch*head), hd=64 ----------------
// Writes output as packed hi/lo tiles (consumer K = DIMN -> 16 tiles per row-blk)
#define AR 32
#define AC 64

__global__ __launch_bounds__(256) void attn_kernel(
    const float* __restrict__ qkv,
    __nv_bfloat16* __restrict__ ohi, __nv_bfloat16* __restrict__ olo)
{
    __shared__ float Qs [AR][HD];
    __shared__ float Kts[HD][AC];
    __shared__ float Vs [AC][HD];
    __shared__ float Ps [AR][AC];

    const int tid = threadIdx.x;
    const int bh  = blockIdx.y;
    const int bb  = bh >> 4, h = bh & 15;
    const int q0  = blockIdx.x * AR;
    const size_t base = (size_t)bb * SEQ * 3 * DIMN;
    const int hoff = h * HD;

    for (int i = tid; i < AR * (HD / 4); i += 256) {
        const int r = i >> 4, c4 = (i & 15) << 2;
        const float4 v = *reinterpret_cast<const float4*>(
            qkv + base + (size_t)(q0 + r) * (3 * DIMN) + hoff + c4);
        Qs[r][c4 + 0] = v.x * ASCALE; Qs[r][c4 + 1] = v.y * ASCALE;
        Qs[r][c4 + 2] = v.z * ASCALE; Qs[r][c4 + 3] = v.w * ASCALE;
    }

    const int tx = tid & 15, ty = tid >> 4;
    const int r0 = ty << 1;
    const int c0 = tx << 2;

    float m0 = -1e30f, m1 = -1e30f, l0 = 0.f, l1 = 0.f;
    float o0[4] = {0.f, 0.f, 0.f, 0.f}, o1[4] = {0.f, 0.f, 0.f, 0.f};

    for (int kb = 0; kb < SEQ; kb += AC) {
        __syncthreads();
        for (int i = tid; i < AC * (HD / 4); i += 256) {
            const int c = i >> 4, d4 = (i & 15) << 2;
            const float* rowp = qkv + base + (size_t)(kb + c) * (3 * DIMN) + hoff;
            const float4 kv = *reinterpret_cast<const float4*>(rowp + DIMN + d4);
            Kts[d4 + 0][c] = kv.x; Kts[d4 + 1][c] = kv.y;
            Kts[d4 + 2][c] = kv.z; Kts[d4 + 3][c] = kv.w;
            *reinterpret_cast<float4*>(&Vs[c][d4]) =
                *reinterpret_cast<const float4*>(rowp + 2 * DIMN + d4);
        }
        __syncthreads();

        float s0[4] = {0.f, 0.f, 0.f, 0.f}, s1[4] = {0.f, 0.f, 0.f, 0.f};
        #pragma unroll
        for (int kd = 0; kd < HD; kd += 4) {
            float qa[4], qb[4];
            *reinterpret_cast<float4*>(qa) = *reinterpret_cast<const float4*>(&Qs[r0][kd]);
            *reinterpret_cast<float4*>(qb) = *reinterpret_cast<const float4*>(&Qs[r0 + 1][kd]);
            #pragma unroll
            for (int u = 0; u < 4; u++) {
                float kf[4];
                *reinterpret_cast<float4*>(kf) = *reinterpret_cast<const float4*>(&Kts[kd + u][c0]);
                #pragma unroll
                for (int j = 0; j < 4; j++) {
                    s0[j] = fmaf(qa[u], kf[j], s0[j]);
                    s1[j] = fmaf(qb[u], kf[j], s1[j]);
                }
            }
        }
        float rm0 = fmaxf(fmaxf(s0[0], s0[1]), fmaxf(s0[2], s0[3]));
        float rm1 = fmaxf(fmaxf(s1[0], s1[1]), fmaxf(s1[2], s1[3]));
        #pragma unroll
        for (int off = 8; off; off >>= 1) {
            rm0 = fmaxf(rm0, __shfl_xor_sync(0xffffffffu, rm0, off));
            rm1 = fmaxf(rm1, __shfl_xor_sync(0xffffffffu, rm1, off));
        }
        const float mn0 = fmaxf(m0, rm0), mn1 = fmaxf(m1, rm1);
        const float al0 = __expf(m0 - mn0), al1 = __expf(m1 - mn1);
        m0 = mn0; m1 = mn1;
        float rs0 = 0.f, rs1 = 0.f;
        #pragma unroll
        for (int j = 0; j < 4; j++) {
            s0[j] = __expf(s0[j] - mn0); rs0 += s0[j];
            s1[j] = __expf(s1[j] - mn1); rs1 += s1[j];
        }
        #pragma unroll
        for (int off = 8; off; off >>= 1) {
            rs0 += __shfl_xor_sync(0xffffffffu, rs0, off);
            rs1 += __shfl_xor_sync(0xffffffffu, rs1, off);
        }
        l0 = l0 * al0 + rs0; l1 = l1 * al1 + rs1;
        #pragma unroll
        for (int j = 0; j < 4; j++) { o0[j] *= al0; o1[j] *= al1; }
        *reinterpret_cast<float4*>(&Ps[r0][c0])     = make_float4(s0[0], s0[1], s0[2], s0[3]);
        *reinterpret_cast<float4*>(&Ps[r0 + 1][c0]) = make_float4(s1[0], s1[1], s1[2], s1[3]);
        __syncthreads();

        #pragma unroll
        for (int c = 0; c < AC; c += 4) {
            float pa[4], pb[4];
            *reinterpret_cast<float4*>(pa) = *reinterpret_cast<const float4*>(&Ps[r0][c]);
            *reinterpret_cast<float4*>(pb) = *reinterpret_cast<const float4*>(&Ps[r0 + 1][c]);
            #pragma unroll
            for (int u = 0; u < 4; u++) {
                float vf[4];
                *reinterpret_cast<float4*>(vf) = *reinterpret_cast<const float4*>(&Vs[c + u][c0]);
                #pragma unroll
                for (int j = 0; j < 4; j++) {
                    o0[j] = fmaf(pa[u], vf[j], o0[j]);
                    o1[j] = fmaf(pb[u], vf[j], o1[j]);
                }
            }
        }
    }

    const float il0 = 1.0f / l0, il1 = 1.0f / l1;
    const int k0 = hoff + c0;
    #pragma unroll
    for (int rr = 0; rr < 2; rr++) {
        const int r = (bb * SEQ + q0) + r0 + rr;
        const float* ov = rr ? o1 : o0;
        const float il = rr ? il1 : il0;
        uint32_t h0, lo0, h1, lo1;
        pack2(ov[0] * il, ov[1] * il, h0, lo0);
        pack2(ov[2] * il, ov[3] * il, h1, lo1);
        const size_t tile = (size_t)(r >> 7) * (DIMN / 64) + (k0 >> 6);
        const uint32_t off = SWZ((uint32_t)((r & 127) * 128 + ((k0 & 63) << 1)));
        *reinterpret_cast<uint2*>((char*)ohi + tile * 16384 + off) = make_uint2(h0, h1);
        *reinterpret_cast<uint2*>((char*)olo + tile * 16384 + off) = make_uint2(lo0, lo1);
    }
}

// ---------------- launch ----------------
extern "C" void kernel_launch(void* const* d_in, const int* in_sizes, int n_in,
                              void* d_out, int out_size)
{
    const float* x    = (const float*)d_in[0];
    const float* Wqkv = (const float*)d_in[1];
    const float* Wout = (const float*)d_in[2];
    const float* bout = (const float*)d_in[3];
    const float* ln1g = (const float*)d_in[4];
    const float* ln1b = (const float*)d_in[5];
    const float* ln2g = (const float*)d_in[6];
    const float* ln2b = (const float*)d_in[7];
    const float* W1   = (const float*)d_in[8];
    const float* b1   = (const float*)d_in[9];
    const float* W2   = (const float*)d_in[10];
    const float* b2   = (const float*)d_in[11];
    float* h = (float*)d_out;

    float* qkv;
    cudaGetSymbolAddress((void**)&qkv, g_qkv);
    __nv_bfloat16 *yh, *yl, *ath, *atl, *uh, *ul;
    cudaGetSymbolAddress((void**)&yh,  g_y_hi);
    cudaGetSymbolAddress((void**)&yl,  g_y_lo);
    cudaGetSymbolAddress((void**)&ath, g_at_hi);
    cudaGetSymbolAddress((void**)&atl, g_at_lo);
    cudaGetSymbolAddress((void**)&uh,  g_u_hi);
    cudaGetSymbolAddress((void**)&ul,  g_u_lo);
    __nv_bfloat16 *qh, *ql, *oh, *ol, *w1h, *w1l, *w2h, *w2l;
    cudaGetSymbolAddress((void**)&qh,  g_qkv_hi);
    cudaGetSymbolAddress((void**)&ql,  g_qkv_lo);
    cudaGetSymbolAddress((void**)&oh,  g_wo_hi);
    cudaGetSymbolAddress((void**)&ol,  g_wo_lo);
    cudaGetSymbolAddress((void**)&w1h, g_w1_hi);
    cudaGetSymbolAddress((void**)&w1l, g_w1_lo);
    cudaGetSymbolAddress((void**)&w2h, g_w2_hi);
    cudaGetSymbolAddress((void**)&w2l, g_w2_lo);

    cudaFuncSetAttribute(gemm_mma, cudaFuncAttributeMaxDynamicSharedMemorySize, GEMM_SMEM);

    // pack all weights (hi/lo bf16, transposed+swizzled tiles)
    prep_kernel<<<dim3(3 * DIMN / 128, DIMN / 64, DEPTH), 256>>>(Wqkv, qh, ql, DIMN, 3 * DIMN);
    prep_kernel<<<dim3(DIMN / 128,     DIMN / 64, DEPTH), 256>>>(Wout, oh, ol, DIMN, DIMN);
    prep_kernel<<<dim3(MLPD / 128,     DIMN / 64, DEPTH), 256>>>(W1,   w1h, w1l, DIMN, MLPD);
    prep_kernel<<<dim3(DIMN / 128,     MLPD / 64, DEPTH), 256>>>(W2,   w2h, w2l, MLPD, DIMN);

    cudaMemcpyAsync(h, x, (size_t)TOK * DIMN * sizeof(float), cudaMemcpyDeviceToDevice);

    for (int l = 0; l < DEPTH; l++) {
        const size_t woffQ = (size_t)l * DIMN * 3 * DIMN;
        const size_t woffO = (size_t)l * DIMN * DIMN;
        const size_t woff1 = (size_t)l * DIMN * MLPD;
        const size_t woff2 = (size_t)l * MLPD * DIMN;
        const float* bo  = bout + (size_t)l * DIMN;
        const float* g1  = ln1g + (size_t)l * DIMN;
        const float* bb1 = ln1b + (size_t)l * DIMN;
        const float* g2  = ln2g + (size_t)l * DIMN;
        const float* bb2 = ln2b + (size_t)l * DIMN;
        const float* bf1 = b1   + (size_t)l * MLPD;
        const float* bf2 = b2   + (size_t)l * DIMN;

        ln_pack<<<TOK, 256>>>(h, g1, bb1, yh, yl);
        gemm_mma<<<dim3(3 * DIMN / 128, TOK / 128), 256, GEMM_SMEM>>>(
            TOK, 3 * DIMN, DIMN, yh, yl, qh + woffQ, ql + woffQ,
            qkv, nullptr, nullptr, nullptr, 0, 0);
        attn_kernel<<<dim3(SEQ / AR, BATCH * HEADS), 256>>>(qkv, ath, atl);
        gemm_mma<<<dim3(DIMN / 128, TOK / 128), 256, GEMM_SMEM>>>(
            TOK, DIMN, DIMN, ath, atl, oh + woffO, ol + woffO,
            h, bo, nullptr, nullptr, 0, FLAG_RESID);
        ln_pack<<<TOK, 256>>>(h, g2, bb2, yh, yl);
        gemm_mma<<<dim3(MLPD / 128, TOK / 128), 256, GEMM_SMEM>>>(
            TOK, MLPD, DIMN, yh, yl, w1h + woff1, w1l + woff1,
            nullptr, bf1, uh, ul, MLPD / 64, FLAG_GELU | FLAG_PACK);
        gemm_mma<<<dim3(DIMN / 128, TOK / 128), 256, GEMM_SMEM>>>(
            TOK, DIMN, MLPD, uh, ul, w2h + woff2, w2l + woff2,
            h, bf2, nullptr, nullptr, 0, FLAG_RESID);
    }
}

// round 11
// speedup vs baseline: 3.5945x; 2.2513x over previous
#include <cuda_runtime.h>
#include <cuda_bf16.h>
#include <math.h>
#include <stdint.h>

// ---------------- problem constants ----------------
#define DIMN   1024
#define SEQ    2048
#define BATCH  2
#define TOK    (BATCH*SEQ)    // 4096 tokens
#define HEADS  16
#define HD     64
#define MLPD   4096
#define DEPTH  6
#define ASCALE 0.03125f       // DIM^-0.5 (reference uses full dim)

#define FLAG_RESID 1
#define FLAG_GELU  2
#define FLAG_PACK  4

// SW128 swizzle (Swizzle<3,4,3>) on byte offsets within a 128B-row tile
#define SWZ(o) ((o) ^ (((o) >> 3) & 0x70))

// ---------------- scratch (device globals; no cudaMalloc allowed) ----------------
// packed hi/lo bf16 activations (tile = 128 rows x 64 k, SW128, 8192 elems)
__device__ __nv_bfloat16 g_y_hi [(size_t)TOK * DIMN];
__device__ __nv_bfloat16 g_y_lo [(size_t)TOK * DIMN];
__device__ __nv_bfloat16 g_qp_hi[(size_t)TOK * 3 * DIMN];   // packed QKV
__device__ __nv_bfloat16 g_qp_lo[(size_t)TOK * 3 * DIMN];
__device__ __nv_bfloat16 g_at_hi[(size_t)TOK * DIMN];
__device__ __nv_bfloat16 g_at_lo[(size_t)TOK * DIMN];
__device__ __nv_bfloat16 g_u_hi [(size_t)TOK * MLPD];
__device__ __nv_bfloat16 g_u_lo [(size_t)TOK * MLPD];
// packed (pre-transposed [N,K], pre-swizzled, bf16 hi/lo) weights
__device__ __nv_bfloat16 g_qkv_hi[(size_t)DEPTH * DIMN * 3 * DIMN];
__device__ __nv_bfloat16 g_qkv_lo[(size_t)DEPTH * DIMN * 3 * DIMN];
__device__ __nv_bfloat16 g_wo_hi [(size_t)DEPTH * DIMN * DIMN];
__device__ __nv_bfloat16 g_wo_lo [(size_t)DEPTH * DIMN * DIMN];
__device__ __nv_bfloat16 g_w1_hi [(size_t)DEPTH * DIMN * MLPD];
__device__ __nv_bfloat16 g_w1_lo [(size_t)DEPTH * DIMN * MLPD];
__device__ __nv_bfloat16 g_w2_hi [(size_t)DEPTH * MLPD * DIMN];
__device__ __nv_bfloat16 g_w2_lo [(size_t)DEPTH * MLPD * DIMN];

// ---------------- helpers ----------------
__device__ __forceinline__ uint32_t smem_u32(const void* p) {
    uint32_t a;
    asm("{ .reg .u64 t; cvta.to.shared.u64 t, %1; cvt.u32.u64 %0, t; }"
        : "=r"(a) : "l"(p));
    return a;
}
__device__ __forceinline__ void cpasync16(uint32_t s, const void* g) {
    asm volatile("cp.async.cg.shared.global [%0], [%1], 16;" :: "r"(s), "l"(g));
}
#define CP_COMMIT() asm volatile("cp.async.commit_group;" ::: "memory")
#define CP_WAIT(n)  asm volatile("cp.async.wait_group %0;" :: "n"(n) : "memory")

#define LDM_X4(r, a)                                                          \
    asm volatile("ldmatrix.sync.aligned.m8n8.x4.shared.b16 {%0,%1,%2,%3}, [%4];" \
                 : "=r"((r)[0]), "=r"((r)[1]), "=r"((r)[2]), "=r"((r)[3])     \
                 : "r"(a))
#define LDM_X4T(r, a)                                                         \
    asm volatile("ldmatrix.sync.aligned.m8n8.x4.trans.shared.b16 {%0,%1,%2,%3}, [%4];" \
                 : "=r"((r)[0]), "=r"((r)[1]), "=r"((r)[2]), "=r"((r)[3])     \
                 : "r"(a))

__device__ __forceinline__ void mma_bf(float* c, const uint32_t* a,
                                       uint32_t b0, uint32_t b1) {
    asm volatile(
        "mma.sync.aligned.m16n8k16.row.col.f32.bf16.bf16.f32 "
        "{%0,%1,%2,%3}, {%4,%5,%6,%7}, {%8,%9}, {%0,%1,%2,%3};"
        : "+f"(c[0]), "+f"(c[1]), "+f"(c[2]), "+f"(c[3])
        : "r"(a[0]), "r"(a[1]), "r"(a[2]), "r"(a[3]), "r"(b0), "r"(b1));
}

__device__ __forceinline__ float gelu_exact(float x) {
    return 0.5f * x * (1.0f + erff(x * 0.70710678118654752f));
}
// pack two floats -> hi bf16 pair / lo bf16 pair
__device__ __forceinline__ void pack2(float a, float b, uint32_t& h, uint32_t& l) {
    const __nv_bfloat16 ha = __float2bfloat16(a);
    const __nv_bfloat16 hb = __float2bfloat16(b);
    const __nv_bfloat16 la = __float2bfloat16(a - __bfloat162float(ha));
    const __nv_bfloat16 lb = __float2bfloat16(b - __bfloat162float(hb));
    h = (uint32_t)__bfloat16_as_ushort(ha) | ((uint32_t)__bfloat16_as_ushort(hb) << 16);
    l = (uint32_t)__bfloat16_as_ushort(la) | ((uint32_t)__bfloat16_as_ushort(lb) << 16);
}

// ---------------- layernorm -> packed hi/lo tiles ----------------
__global__ __launch_bounds__(256) void ln_pack(
    const float* __restrict__ x, const float* __restrict__ g,
    const float* __restrict__ b, __nv_bfloat16* __restrict__ hi,
    __nv_bfloat16* __restrict__ lo)
{
    __shared__ float redS[8], redQ[8];
    const int row = blockIdx.x;
    const int tid = threadIdx.x;
    const float4 v = reinterpret_cast<const float4*>(x)[(size_t)row * 256 + tid];
    float s = v.x + v.y + v.z + v.w;
    float q = v.x*v.x + v.y*v.y + v.z*v.z + v.w*v.w;
    #pragma unroll
    for (int off = 16; off; off >>= 1) {
        s += __shfl_xor_sync(0xffffffffu, s, off);
        q += __shfl_xor_sync(0xffffffffu, q, off);
    }
    if ((tid & 31) == 0) { redS[tid >> 5] = s; redQ[tid >> 5] = q; }
    __syncthreads();
    s = 0.f; q = 0.f;
    #pragma unroll
    for (int w = 0; w < 8; w++) { s += redS[w]; q += redQ[w]; }
    const float mean = s * (1.0f / DIMN);
    const float var  = q * (1.0f / DIMN) - mean * mean;
    const float rstd = rsqrtf(var + 1e-5f);
    const float4 gg = reinterpret_cast<const float4*>(g)[tid];
    const float4 bb = reinterpret_cast<const float4*>(b)[tid];
    float o0 = (v.x - mean) * rstd * gg.x + bb.x;
    float o1 = (v.y - mean) * rstd * gg.y + bb.y;
    float o2 = (v.z - mean) * rstd * gg.z + bb.z;
    float o3 = (v.w - mean) * rstd * gg.w + bb.w;
    uint32_t h0, l0, h1, l1;
    pack2(o0, o1, h0, l0);
    pack2(o2, o3, h1, l1);
    const int k = tid << 2;
    const size_t tile = (size_t)(row >> 7) * (DIMN / 64) + (k >> 6);
    const uint32_t off = SWZ((uint32_t)((row & 127) * 128 + ((k & 63) << 1)));
    *reinterpret_cast<uint2*>((char*)hi + tile * 16384 + off) = make_uint2(h0, h1);
    *reinterpret_cast<uint2*>((char*)lo + tile * 16384 + off) = make_uint2(l0, l1);
}

// ---------------- weight prep: fp32 W[K,N] -> packed hi/lo bf16 tiles ----------
__global__ __launch_bounds__(256) void prep_kernel(
    const float* __restrict__ W, __nv_bfloat16* __restrict__ hi,
    __nv_bfloat16* __restrict__ lo, int K, int N)
{
    __shared__ __nv_bfloat16 shH[8192], shL[8192];
    const int nt = blockIdx.x, kc = blockIdx.y, layer = blockIdx.z;
    const float* Wp = W + (size_t)layer * K * N;
    const int tid = threadIdx.x;
    #pragma unroll
    for (int i = 0; i < 8; i++) {
        const int idx = tid + (i << 8);
        const int r  = idx >> 5;               // k_local 0..63
        const int c4 = (idx & 31) << 2;        // n_local 0..124
        const float4 v = *reinterpret_cast<const float4*>(
            Wp + (size_t)(kc * 64 + r) * N + nt * 128 + c4);
        const float f[4] = {v.x, v.y, v.z, v.w};
        #pragma unroll
        for (int j = 0; j < 4; j++) {
            const __nv_bfloat16 h = __float2bfloat16(f[j]);
            const __nv_bfloat16 l = __float2bfloat16(f[j] - __bfloat162float(h));
            const uint32_t sw = SWZ((uint32_t)((c4 + j) * 128 + r * 2));
            shH[sw >> 1] = h;
            shL[sw >> 1] = l;
        }
    }
    __syncthreads();
    const size_t tb = ((size_t)layer * gridDim.x * gridDim.y +
                       (size_t)nt * gridDim.y + kc) * 8192;
    uint4* dH = reinterpret_cast<uint4*>(hi + tb);
    uint4* dL = reinterpret_cast<uint4*>(lo + tb);
    const uint4* sH = reinterpret_cast<const uint4*>(shH);
    const uint4* sL = reinterpret_cast<const uint4*>(shL);
    #pragma unroll
    for (int i = 0; i < 4; i++) {
        const int idx = tid + (i << 8);
        dH[idx] = sH[idx];
        dL[idx] = sL[idx];
    }
}

// ---------------- mma.sync split-bf16 GEMM ----------------
#define STAGES 3
#define STG_BYTES 65536          // Ahi 16K | Alo 16K | Bhi 16K | Blo 16K
#define GEMM_SMEM (STAGES * STG_BYTES)

__global__ __launch_bounds__(256, 1) void gemm_mma(
    int M, int N, int K,
    const __nv_bfloat16* __restrict__ Ahi, const __nv_bfloat16* __restrict__ Alo,
    const __nv_bfloat16* __restrict__ Bhi, const __nv_bfloat16* __restrict__ Blo,
    float* __restrict__ C, const float* __restrict__ bias,
    __nv_bfloat16* __restrict__ Phi, __nv_bfloat16* __restrict__ Plo,
    int packNC, int flags)
{
    extern __shared__ __align__(1024) char smem[];
    const uint32_t sb = smem_u32(smem);
    const int tid = threadIdx.x;
    const int wid = tid >> 5, lane = tid & 31;
    const int NC = K >> 6;
    const int bm = blockIdx.y << 7, bn = blockIdx.x << 7;
    const size_t at0 = (size_t)blockIdx.y * NC;
    const size_t bt0 = (size_t)blockIdx.x * NC;

    #pragma unroll
    for (int s = 0; s < STAGES; s++) {
        const char* ga_h = (const char*)Ahi + (at0 + s) * 16384;
        const char* ga_l = (const char*)Alo + (at0 + s) * 16384;
        const char* gb_h = (const char*)Bhi + (bt0 + s) * 16384;
        const char* gb_l = (const char*)Blo + (bt0 + s) * 16384;
        const uint32_t ds = sb + s * STG_BYTES;
        #pragma unroll
        for (int i = 0; i < 4; i++) {
            const int idx = (tid + (i << 8)) << 4;
            cpasync16(ds +     0 + idx, ga_h + idx);
            cpasync16(ds + 16384 + idx, ga_l + idx);
            cpasync16(ds + 32768 + idx, gb_h + idx);
            cpasync16(ds + 49152 + idx, gb_l + idx);
        }
        CP_COMMIT();
    }

    float acc[2][8][4];
    #pragma unroll
    for (int i = 0; i < 2; i++)
        #pragma unroll
        for (int j = 0; j < 8; j++)
            #pragma unroll
            for (int u = 0; u < 4; u++) acc[i][j][u] = 0.f;

    const int wm0 = (wid & 3) << 5;
    const int wn0 = (wid >> 2) << 6;
    uint32_t aoff[2], boff[4];
    #pragma unroll
    for (int mt = 0; mt < 2; mt++)
        aoff[mt] = (uint32_t)((wm0 + (mt << 4) + (lane & 15)) * 128 + ((lane >> 4) << 4));
    #pragma unroll
    for (int g = 0; g < 4; g++)
        boff[g] = (uint32_t)((wn0 + (g << 4) + (lane & 7) + ((lane >> 1) & 8)) * 128 +
                             ((lane & 8) << 1));

    for (int c = 0; c < NC; c++) {
        const int n_after = (c + STAGES <= NC ? STAGES : NC - c) - 1;
        if (n_after >= 2) CP_WAIT(2);
        else if (n_after == 1) CP_WAIT(1);
        else CP_WAIT(0);
        __syncthreads();

        const uint32_t stb = sb + (uint32_t)(c % STAGES) * STG_BYTES;
        #pragma unroll
        for (int ks = 0; ks < 4; ks++) {
            const uint32_t kb = (uint32_t)(ks << 5);
            uint32_t ah[2][4], al[2][4], bf[4][4];
            #pragma unroll
            for (int mt = 0; mt < 2; mt++) {
                const uint32_t o = aoff[mt] + kb;
                LDM_X4(ah[mt], stb + SWZ(o));
            }
            #pragma unroll
            for (int g = 0; g < 4; g++) {
                const uint32_t o = boff[g] + kb;
                LDM_X4(bf[g], stb + 32768 + SWZ(o));
            }
            #pragma unroll
            for (int mt = 0; mt < 2; mt++)
                #pragma unroll
                for (int g = 0; g < 4; g++) {
                    mma_bf(acc[mt][2*g],   ah[mt], bf[g][0], bf[g][1]);
                    mma_bf(acc[mt][2*g+1], ah[mt], bf[g][2], bf[g][3]);
                }
            #pragma unroll
            for (int mt = 0; mt < 2; mt++) {
                const uint32_t o = aoff[mt] + kb;
                LDM_X4(al[mt], stb + 16384 + SWZ(o));
            }
            #pragma unroll
            for (int mt = 0; mt < 2; mt++)
                #pragma unroll
                for (int g = 0; g < 4; g++) {
                    mma_bf(acc[mt][2*g],   al[mt], bf[g][0], bf[g][1]);
                    mma_bf(acc[mt][2*g+1], al[mt], bf[g][2], bf[g][3]);
                }
            #pragma unroll
            for (int g = 0; g < 4; g++) {
                const uint32_t o = boff[g] + kb;
                LDM_X4(bf[g], stb + 49152 + SWZ(o));
            }
            #pragma unroll
            for (int mt = 0; mt < 2; mt++)
                #pragma unroll
                for (int g = 0; g < 4; g++) {
                    mma_bf(acc[mt][2*g],   ah[mt], bf[g][0], bf[g][1]);
                    mma_bf(acc[mt][2*g+1], ah[mt], bf[g][2], bf[g][3]);
                }
        }
        __syncthreads();

        const int cn = c + STAGES;
        if (cn < NC) {
            const char* ga_h = (const char*)Ahi + (at0 + cn) * 16384;
            const char* ga_l = (const char*)Alo + (at0 + cn) * 16384;
            const char* gb_h = (const char*)Bhi + (bt0 + cn) * 16384;
            const char* gb_l = (const char*)Blo + (bt0 + cn) * 16384;
            const uint32_t ds = sb + (uint32_t)(c % STAGES) * STG_BYTES;
            #pragma unroll
            for (int i = 0; i < 4; i++) {
                const int idx = (tid + (i << 8)) << 4;
                cpasync16(ds +     0 + idx, ga_h + idx);
                cpasync16(ds + 16384 + idx, ga_l + idx);
                cpasync16(ds + 32768 + idx, gb_h + idx);
                cpasync16(ds + 49152 + idx, gb_l + idx);
            }
        }
        CP_COMMIT();
    }

    // ---- epilogue ----
    #pragma unroll
    for (int mt = 0; mt < 2; mt++) {
        const int r0 = bm + wm0 + (mt << 4) + (lane >> 2);
        #pragma unroll
        for (int nt = 0; nt < 8; nt++) {
            const int col = bn + wn0 + (nt << 3) + ((lane & 3) << 1);
            float va0 = acc[mt][nt][0], va1 = acc[mt][nt][1];
            float vb0 = acc[mt][nt][2], vb1 = acc[mt][nt][3];
            if (bias) {
                const float2 bv = *reinterpret_cast<const float2*>(bias + col);
                va0 += bv.x; va1 += bv.y; vb0 += bv.x; vb1 += bv.y;
            }
            if (flags & FLAG_GELU) {
                va0 = gelu_exact(va0); va1 = gelu_exact(va1);
                vb0 = gelu_exact(vb0); vb1 = gelu_exact(vb1);
            }
            if (flags & FLAG_PACK) {
                #pragma unroll
                for (int rr = 0; rr < 2; rr++) {
                    const int r = r0 + (rr << 3);
                    const float pa = rr ? vb0 : va0;
                    const float pb = rr ? vb1 : va1;
                    uint32_t hv, lv;
                    pack2(pa, pb, hv, lv);
                    const size_t tile = (size_t)(r >> 7) * packNC + (col >> 6);
                    const uint32_t off = SWZ((uint32_t)((r & 127) * 128 + ((col & 63) << 1)));
                    *reinterpret_cast<uint32_t*>((char*)Phi + tile * 16384 + off) = hv;
                    *reinterpret_cast<uint32_t*>((char*)Plo + tile * 16384 + off) = lv;
                }
            } else {
                float* p0 = C + (size_t)r0 * N + col;
                float* p1 = C + (size_t)(r0 + 8) * N + col;
                if (flags & FLAG_RESID) {
                    const float2 c0 = *reinterpret_cast<const float2*>(p0);
                    const float2 c1 = *reinterpret_cast<const float2*>(p1);
                    va0 += c0.x; va1 += c0.y; vb0 += c1.x; vb1 += c1.y;
                }
                *reinterpret_cast<float2*>(p0) = make_float2(va0, va1);
                *reinterpret_cast<float2*>(p1) = make_float2(vb0, vb1);
            }
        }
    }
}

// ---------------- mma.sync flash attention, split-bf16, hd=64 ----------------
// CTA: 128 threads (4 warps), 64 q-rows, kv tiles of 64, double-buffered K/V.
// Inputs: packed hi/lo QKV tiles (packNC=48). Output: packed hi/lo (packNC=16).
#define ATT_SMEM (16384 + 2 * 32768)   // Q(hi+lo) + 2 stages * (K/V hi+lo)

__global__ __launch_bounds__(128, 2) void attn_mma(
    const __nv_bfloat16* __restrict__ qkvh, const __nv_bfloat16* __restrict__ qkvl,
    __nv_bfloat16* __restrict__ ohi, __nv_bfloat16* __restrict__ olo)
{
    extern __shared__ __align__(1024) char asmem[];
    const uint32_t sb = smem_u32(asmem);
    const int tid = threadIdx.x;
    const int wid = tid >> 5, lane = tid & 31;
    const int bh = blockIdx.y;
    const int bb = bh >> 4, h = bh & 15;
    const int q0 = blockIdx.x << 6;                 // seq-local
    const int grow0 = bb * SEQ + q0;                // global token row
    const int hq = h;                               // Q col-tile
    const int hk = (DIMN >> 6) + h;                 // K col-tile
    const int hv = (2 * DIMN >> 6) + h;             // V col-tile

    // 64-row source block inside a packed 128-row tile (contiguous 8KB)
    auto src64 = [&](const __nv_bfloat16* base, int coltile, int grows) -> const char* {
        return (const char*)base + ((size_t)(grows >> 7) * 48 + coltile) * 16384
               + (size_t)(grows & 127) * 128;
    };

    // ---- prologue: Q (hi+lo) + KV stage 0 ----
    {
        const char* qh_ = src64(qkvh, hq, grow0);
        const char* ql_ = src64(qkvl, hq, grow0);
        #pragma unroll
        for (int i = 0; i < 4; i++) {
            const int idx = (tid + (i << 7)) << 4;   // 0..8176
            cpasync16(sb +        idx, qh_ + idx);
            cpasync16(sb + 8192 + idx, ql_ + idx);
        }
        const int gkv = bb * SEQ;                    // kv0 = 0
        const char* kh_ = src64(qkvh, hk, gkv);
        const char* kl_ = src64(qkvl, hk, gkv);
        const char* vh_ = src64(qkvh, hv, gkv);
        const char* vl_ = src64(qkvl, hv, gkv);
        const uint32_t ds = sb + 16384;
        #pragma unroll
        for (int i = 0; i < 4; i++) {
            const int idx = (tid + (i << 7)) << 4;
            cpasync16(ds +         idx, kh_ + idx);
            cpasync16(ds +  8192 + idx, kl_ + idx);
            cpasync16(ds + 16384 + idx, vh_ + idx);
            cpasync16(ds + 24576 + idx, vl_ + idx);
        }
        CP_COMMIT();
    }
    CP_WAIT(0);
    __syncthreads();

    // ---- preload Q fragments (fixed for whole CTA lifetime) ----
    const uint32_t aoff = (uint32_t)(((wid << 4) + (lane & 15)) * 128 + ((lane >> 4) << 4));
    uint32_t qhf[4][4], qlf[4][4];
    #pragma unroll
    for (int kb = 0; kb < 4; kb++) {
        LDM_X4(qhf[kb], sb +        SWZ(aoff + (kb << 5)));
        LDM_X4(qlf[kb], sb + 8192 + SWZ(aoff + (kb << 5)));
    }

    uint32_t boffK[4], voffV[4];
    #pragma unroll
    for (int g = 0; g < 4; g++) {
        boffK[g] = (uint32_t)(((g << 4) + (lane & 7) + ((lane >> 1) & 8)) * 128 +
                              ((lane & 8) << 1));
        voffV[g] = (uint32_t)((lane & 15) * 128 + ((lane >> 4) << 4) + (g << 5));
    }

    float oacc[8][4];
    #pragma unroll
    for (int j = 0; j < 8; j++)
        #pragma unroll
        for (int u = 0; u < 4; u++) oacc[j][u] = 0.f;
    float m0 = -1e30f, m1 = -1e30f, l0 = 0.f, l1 = 0.f;

    const int NIT = SEQ / 64;
    for (int it = 0; it < NIT; it++) {
        const int st = it & 1;
        // issue next stage
        if (it + 1 < NIT) {
            const int gkv = bb * SEQ + ((it + 1) << 6);
            const char* kh_ = src64(qkvh, hk, gkv);
            const char* kl_ = src64(qkvl, hk, gkv);
            const char* vh_ = src64(qkvh, hv, gkv);
            const char* vl_ = src64(qkvl, hv, gkv);
            const uint32_t ds = sb + 16384 + ((it + 1) & 1) * 32768;
            #pragma unroll
            for (int i = 0; i < 4; i++) {
                const int idx = (tid + (i << 7)) << 4;
                cpasync16(ds +         idx, kh_ + idx);
                cpasync16(ds +  8192 + idx, kl_ + idx);
                cpasync16(ds + 16384 + idx, vh_ + idx);
                cpasync16(ds + 24576 + idx, vl_ + idx);
            }
            CP_COMMIT();
        }

        const uint32_t kbufH = sb + 16384 + st * 32768;
        const uint32_t kbufL = kbufH + 8192;
        const uint32_t vbufH = kbufH + 16384;
        const uint32_t vbufL = kbufH + 24576;

        // ---- S = Q K^T (3-term split) ----
        float sacc[8][4];
        #pragma unroll
        for (int j = 0; j < 8; j++)
            #pragma unroll
            for (int u = 0; u < 4; u++) sacc[j][u] = 0.f;

        #pragma unroll
        for (int kb = 0; kb < 4; kb++) {
            const uint32_t kbb = (uint32_t)(kb << 5);
            uint32_t bh4[4][4];
            #pragma unroll
            for (int g = 0; g < 4; g++)
                LDM_X4(bh4[g], kbufH + SWZ(boffK[g] + kbb));
            #pragma unroll
            for (int g = 0; g < 4; g++) {
                mma_bf(sacc[2*g],   qhf[kb], bh4[g][0], bh4[g][1]);
                mma_bf(sacc[2*g+1], qhf[kb], bh4[g][2], bh4[g][3]);
                mma_bf(sacc[2*g],   qlf[kb], bh4[g][0], bh4[g][1]);
                mma_bf(sacc[2*g+1], qlf[kb], bh4[g][2], bh4[g][3]);
            }
            uint32_t bl4[4][4];
            #pragma unroll
            for (int g = 0; g < 4; g++)
                LDM_X4(bl4[g], kbufL + SWZ(boffK[g] + kbb));
            #pragma unroll
            for (int g = 0; g < 4; g++) {
                mma_bf(sacc[2*g],   qhf[kb], bl4[g][0], bl4[g][1]);
                mma_bf(sacc[2*g+1], qhf[kb], bl4[g][2], bl4[g][3]);
            }
        }

        // ---- online softmax (scale folded here) ----
        #pragma unroll
        for (int j = 0; j < 8; j++)
            #pragma unroll
            for (int u = 0; u < 4; u++) sacc[j][u] *= ASCALE;

        float mx0 = -1e30f, mx1 = -1e30f;
        #pragma unroll
        for (int j = 0; j < 8; j++) {
            mx0 = fmaxf(mx0, fmaxf(sacc[j][0], sacc[j][1]));
            mx1 = fmaxf(mx1, fmaxf(sacc[j][2], sacc[j][3]));
        }
        mx0 = fmaxf(mx0, __shfl_xor_sync(0xffffffffu, mx0, 1));
        mx0 = fmaxf(mx0, __shfl_xor_sync(0xffffffffu, mx0, 2));
        mx1 = fmaxf(mx1, __shfl_xor_sync(0xffffffffu, mx1, 1));
        mx1 = fmaxf(mx1, __shfl_xor_sync(0xffffffffu, mx1, 2));
        const float nm0 = fmaxf(m0, mx0), nm1 = fmaxf(m1, mx1);
        const float al0 = __expf(m0 - nm0), al1 = __expf(m1 - nm1);
        m0 = nm0; m1 = nm1;
        float rs0 = 0.f, rs1 = 0.f;
        #pragma unroll
        for (int j = 0; j < 8; j++) {
            sacc[j][0] = __expf(sacc[j][0] - m0); rs0 += sacc[j][0];
            sacc[j][1] = __expf(sacc[j][1] - m0); rs0 += sacc[j][1];
            sacc[j][2] = __expf(sacc[j][2] - m1); rs1 += sacc[j][2];
            sacc[j][3] = __expf(sacc[j][3] - m1); rs1 += sacc[j][3];
        }
        l0 = l0 * al0 + rs0;
        l1 = l1 * al1 + rs1;
        #pragma unroll
        for (int j = 0; j < 8; j++) {
            oacc[j][0] *= al0; oacc[j][1] *= al0;
            oacc[j][2] *= al1; oacc[j][3] *= al1;
        }

        // ---- O += P V (3-term split; P frags built from sacc in-register) ----
        #pragma unroll
        for (int jp = 0; jp < 4; jp++) {
            uint32_t pah[4], pal[4];
            pack2(sacc[2*jp][0],   sacc[2*jp][1],   pah[0], pal[0]);
            pack2(sacc[2*jp][2],   sacc[2*jp][3],   pah[1], pal[1]);
            pack2(sacc[2*jp+1][0], sacc[2*jp+1][1], pah[2], pal[2]);
            pack2(sacc[2*jp+1][2], sacc[2*jp+1][3], pah[3], pal[3]);
            const uint32_t rowb = (uint32_t)(jp << 11);     // 16 rows * 128B
            #pragma unroll
            for (int g = 0; g < 4; g++) {
                uint32_t vh4[4], vl4[4];
                LDM_X4T(vh4, vbufH + SWZ(voffV[g] + rowb));
                mma_bf(oacc[2*g],   pah, vh4[0], vh4[1]);
                mma_bf(oacc[2*g+1], pah, vh4[2], vh4[3]);
                mma_bf(oacc[2*g],   pal, vh4[0], vh4[1]);
                mma_bf(oacc[2*g+1], pal, vh4[2], vh4[3]);
                LDM_X4T(vl4, vbufL + SWZ(voffV[g] + rowb));
                mma_bf(oacc[2*g],   pah, vl4[0], vl4[1]);
                mma_bf(oacc[2*g+1], pah, vl4[2], vl4[3]);
            }
        }

        if (it + 1 < NIT) CP_WAIT(0);
        __syncthreads();
    }

    // ---- finalize & write packed hi/lo ----
    l0 += __shfl_xor_sync(0xffffffffu, l0, 1);
    l0 += __shfl_xor_sync(0xffffffffu, l0, 2);
    l1 += __shfl_xor_sync(0xffffffffu, l1, 1);
    l1 += __shfl_xor_sync(0xffffffffu, l1, 2);
    const float il0 = 1.0f / l0, il1 = 1.0f / l1;

    const int r0g = grow0 + (wid << 4) + (lane >> 2);
    #pragma unroll
    for (int j = 0; j < 8; j++) {
        const int k0 = h * HD + (j << 3) + ((lane & 3) << 1);
        uint32_t hv0, lv0, hv1, lv1;
        pack2(oacc[j][0] * il0, oacc[j][1] * il0, hv0, lv0);
        pack2(oacc[j][2] * il1, oacc[j][3] * il1, hv1, lv1);
        const size_t t0 = (size_t)(r0g >> 7) * 16 + (k0 >> 6);
        const uint32_t of0 = SWZ((uint32_t)((r0g & 127) * 128 + ((k0 & 63) << 1)));
        *reinterpret_cast<uint32_t*>((char*)ohi + t0 * 16384 + of0) = hv0;
        *reinterpret_cast<uint32_t*>((char*)olo + t0 * 16384 + of0) = lv0;
        const int r1g = r0g + 8;
        const size_t t1 = (size_t)(r1g >> 7) * 16 + (k0 >> 6);
        const uint32_t of1 = SWZ((uint32_t)((r1g & 127) * 128 + ((k0 & 63) << 1)));
        *reinterpret_cast<uint32_t*>((char*)ohi + t1 * 16384 + of1) = hv1;
        *reinterpret_cast<uint32_t*>((char*)olo + t1 * 16384 + of1) = lv1;
    }
}

// ---------------- launch ----------------
extern "C" void kernel_launch(void* const* d_in, const int* in_sizes, int n_in,
                              void* d_out, int out_size)
{
    const float* x    = (const float*)d_in[0];
    const float* Wqkv = (const float*)d_in[1];
    const float* Wout = (const float*)d_in[2];
    const float* bout = (const float*)d_in[3];
    const float* ln1g = (const float*)d_in[4];
    const float* ln1b = (const float*)d_in[5];
    const float* ln2g = (const float*)d_in[6];
    const float* ln2b = (const float*)d_in[7];
    const float* W1   = (const float*)d_in[8];
    const float* b1   = (const float*)d_in[9];
    const float* W2   = (const float*)d_in[10];
    const float* b2   = (const float*)d_in[11];
    float* h = (float*)d_out;

    __nv_bfloat16 *yh, *yl, *qph, *qpl, *ath, *atl, *uh, *ul;
    cudaGetSymbolAddress((void**)&yh,  g_y_hi);
    cudaGetSymbolAddress((void**)&yl,  g_y_lo);
    cudaGetSymbolAddress((void**)&qph, g_qp_hi);
    cudaGetSymbolAddress((void**)&qpl, g_qp_lo);
    cudaGetSymbolAddress((void**)&ath, g_at_hi);
    cudaGetSymbolAddress((void**)&atl, g_at_lo);
    cudaGetSymbolAddress((void**)&uh,  g_u_hi);
    cudaGetSymbolAddress((void**)&ul,  g_u_lo);
    __nv_bfloat16 *qh, *ql, *oh, *ol, *w1h, *w1l, *w2h, *w2l;
    cudaGetSymbolAddress((void**)&qh,  g_qkv_hi);
    cudaGetSymbolAddress((void**)&ql,  g_qkv_lo);
    cudaGetSymbolAddress((void**)&oh,  g_wo_hi);
    cudaGetSymbolAddress((void**)&ol,  g_wo_lo);
    cudaGetSymbolAddress((void**)&w1h, g_w1_hi);
    cudaGetSymbolAddress((void**)&w1l, g_w1_lo);
    cudaGetSymbolAddress((void**)&w2h, g_w2_hi);
    cudaGetSymbolAddress((void**)&w2l, g_w2_lo);

    cudaFuncSetAttribute(gemm_mma, cudaFuncAttributeMaxDynamicSharedMemorySize, GEMM_SMEM);
    cudaFuncSetAttribute(attn_mma, cudaFuncAttributeMaxDynamicSharedMemorySize, ATT_SMEM);

    prep_kernel<<<dim3(3 * DIMN / 128, DIMN / 64, DEPTH), 256>>>(Wqkv, qh, ql, DIMN, 3 * DIMN);
    prep_kernel<<<dim3(DIMN / 128,     DIMN / 64, DEPTH), 256>>>(Wout, oh, ol, DIMN, DIMN);
    prep_kernel<<<dim3(MLPD / 128,     DIMN / 64, DEPTH), 256>>>(W1,   w1h, w1l, DIMN, MLPD);
    prep_kernel<<<dim3(DIMN / 128,     MLPD / 64, DEPTH), 256>>>(W2,   w2h, w2l, MLPD, DIMN);

    cudaMemcpyAsync(h, x, (size_t)TOK * DIMN * sizeof(float), cudaMemcpyDeviceToDevice);

    for (int l = 0; l < DEPTH; l++) {
        const size_t woffQ = (size_t)l * DIMN * 3 * DIMN;
        const size_t woffO = (size_t)l * DIMN * DIMN;
        const size_t woff1 = (size_t)l * DIMN * MLPD;
        const size_t woff2 = (size_t)l * MLPD * DIMN;
        const float* bo  = bout + (size_t)l * DIMN;
        const float* g1  = ln1g + (size_t)l * DIMN;
        const float* bb1 = ln1b + (size_t)l * DIMN;
        const float* g2  = ln2g + (size_t)l * DIMN;
        const float* bb2 = ln2b + (size_t)l * DIMN;
        const float* bf1 = b1   + (size_t)l * MLPD;
        const float* bf2 = b2   + (size_t)l * DIMN;

        ln_pack<<<TOK, 256>>>(h, g1, bb1, yh, yl);
        gemm_mma<<<dim3(3 * DIMN / 128, TOK / 128), 256, GEMM_SMEM>>>(
            TOK, 3 * DIMN, DIMN, yh, yl, qh + woffQ, ql + woffQ,
            nullptr, nullptr, qph, qpl, 3 * DIMN / 64, FLAG_PACK);
        attn_mma<<<dim3(SEQ / 64, BATCH * HEADS), 128, ATT_SMEM>>>(qph, qpl, ath, atl);
        gemm_mma<<<dim3(DIMN / 128, TOK / 128), 256, GEMM_SMEM>>>(
            TOK, DIMN, DIMN, ath, atl, oh + woffO, ol + woffO,
            h, bo, nullptr, nullptr, 0, FLAG_RESID);
        ln_pack<<<TOK, 256>>>(h, g2, bb2, yh, yl);
        gemm_mma<<<dim3(MLPD / 128, TOK / 128), 256, GEMM_SMEM>>>(
            TOK, MLPD, DIMN, yh, yl, w1h + woff1, w1l + woff1,
            nullptr, bf1, uh, ul, MLPD / 64, FLAG_GELU | FLAG_PACK);
        gemm_mma<<<dim3(DIMN / 128, TOK / 128), 256, GEMM_SMEM>>>(
            TOK, DIMN, MLPD, uh, ul, w2h + woff2, w2l + woff2,
            h, bf2, nullptr, nullptr, 0, FLAG_RESID);
    }
}